// round 1
// baseline (speedup 1.0000x reference)
#include <cuda_runtime.h>
#include <mma.h>

using namespace nvcuda;

// Problem constants
#define BATCH   2
#define SEQ     8192
#define DMODEL  1024
#define NHEADS  16
#define HD      64
#define NBLK    64      // SEQ / 128
#define BS      128     // block size = window

// ---------------------------------------------------------------------------
// Device scratch (allocation-free rule: __device__ globals)
// ---------------------------------------------------------------------------
__device__ float g_q[(size_t)BATCH * NHEADS * SEQ * HD];     // 64 MB
__device__ float g_k[(size_t)BATCH * NHEADS * SEQ * HD];     // 64 MB
__device__ float g_v[(size_t)BATCH * NHEADS * SEQ * HD];     // 64 MB
__device__ float g_attn[(size_t)BATCH * SEQ * DMODEL];       // 64 MB

// ---------------------------------------------------------------------------
// tf32 helpers
// ---------------------------------------------------------------------------
template <typename Frag>
__device__ __forceinline__ void frag_to_tf32(Frag& f) {
#pragma unroll
    for (int i = 0; i < f.num_elements; i++)
        f.x[i] = wmma::__float_to_tf32(f.x[i]);
}

// ---------------------------------------------------------------------------
// GEMM: C[M,N] = A[M,K] @ W[N,K]^T + bias   (M=16384, N=K=1024)
// LAYOUT 0: C row-major [M,N]
// LAYOUT 1: C as [B,H,S,hd]  (n -> h=n/64, d=n%64 ; m -> b=m/SEQ, s=m%SEQ)
// Tiles: BM=128, BN=128, BK=32. 256 threads = 8 warps (4x2), warp tile 32x64.
// ---------------------------------------------------------------------------
template <int LAYOUT>
__global__ void __launch_bounds__(256, 2)
gemm_tf32_kernel(const float* __restrict__ A, const float* __restrict__ W,
                 const float* __restrict__ bias, float* __restrict__ C)
{
    extern __shared__ float sh[];
    float* As = sh;               // [128][36]
    float* Bs = sh + 128 * 36;    // [128][36]

    const int tid  = threadIdx.x;
    const int warp = tid >> 5;
    const int wm   = warp & 3;    // 0..3 (row group of 32)
    const int wn   = warp >> 2;   // 0..1 (col group of 64)
    const int m0   = blockIdx.y * 128;
    const int n0   = blockIdx.x * 128;

    wmma::fragment<wmma::accumulator, 16, 16, 8, float> acc[2][4];
#pragma unroll
    for (int i = 0; i < 2; i++)
#pragma unroll
        for (int j = 0; j < 4; j++)
            wmma::fill_fragment(acc[i][j], 0.0f);

    for (int k0 = 0; k0 < DMODEL; k0 += 32) {
        // cooperative tile loads (float4)
#pragma unroll
        for (int i = 0; i < 4; i++) {
            int idx = tid + i * 256;          // 1024 float4 per matrix
            int r   = idx >> 3;
            int c4  = (idx & 7) << 2;
            *(float4*)&As[r * 36 + c4] =
                *(const float4*)&A[(size_t)(m0 + r) * DMODEL + k0 + c4];
            *(float4*)&Bs[r * 36 + c4] =
                *(const float4*)&W[(size_t)(n0 + r) * DMODEL + k0 + c4];
        }
        __syncthreads();

#pragma unroll
        for (int ks = 0; ks < 4; ks++) {
            wmma::fragment<wmma::matrix_a, 16, 16, 8, wmma::precision::tf32, wmma::row_major> af[2];
            wmma::fragment<wmma::matrix_b, 16, 16, 8, wmma::precision::tf32, wmma::col_major> bf[4];
#pragma unroll
            for (int i = 0; i < 2; i++) {
                wmma::load_matrix_sync(af[i], &As[(wm * 32 + i * 16) * 36 + ks * 8], 36);
                frag_to_tf32(af[i]);
            }
#pragma unroll
            for (int j = 0; j < 4; j++) {
                wmma::load_matrix_sync(bf[j], &Bs[(wn * 64 + j * 16) * 36 + ks * 8], 36);
                frag_to_tf32(bf[j]);
            }
#pragma unroll
            for (int i = 0; i < 2; i++)
#pragma unroll
                for (int j = 0; j < 4; j++)
                    wmma::mma_sync(acc[i][j], af[i], bf[j], acc[i][j]);
        }
        __syncthreads();
    }

    // Epilogue: stage to smem (reuse load buffers), then bias-add + layout write
    float* stg = sh;  // [128][132]
#pragma unroll
    for (int i = 0; i < 2; i++)
#pragma unroll
        for (int j = 0; j < 4; j++)
            wmma::store_matrix_sync(&stg[(wm * 32 + i * 16) * 132 + wn * 64 + j * 16],
                                    acc[i][j], 132, wmma::mem_row_major);
    __syncthreads();

#pragma unroll
    for (int i = 0; i < 16; i++) {
        int idx = tid + i * 256;         // 4096 float4 total
        int r   = idx >> 5;
        int c4  = (idx & 31) << 2;
        float4 v = *(float4*)&stg[r * 132 + c4];
        float4 bi = *(const float4*)&bias[n0 + c4];
        v.x += bi.x; v.y += bi.y; v.z += bi.z; v.w += bi.w;

        if (LAYOUT == 0) {
            *(float4*)&C[(size_t)(m0 + r) * DMODEL + n0 + c4] = v;
        } else {
            int m = m0 + r;
            int bb = m >> 13;            // / SEQ
            int s  = m & (SEQ - 1);
            int n  = n0 + c4;
            int h  = n >> 6;
            int d  = n & 63;
            *(float4*)&g_q[0] ; // (no-op placeholder removed by compiler)
            *(float4*)&C[(((size_t)bb * NHEADS + h) * SEQ + s) * HD + d] = v;
        }
    }
}

// ---------------------------------------------------------------------------
// Attention kernel: one CTA per (b, h, block n). 256 threads = 8 warps.
// Computes O[128, 64] = softmax(mask(Q Kctx^T / 8)) @ Vctx
// SMEM: scores [128][388] fp32 + K/V buffer [128][64] + row_inv[128]
// ---------------------------------------------------------------------------
#define SC_LD 388

__global__ void __launch_bounds__(256, 1)
attn_kernel(const float* __restrict__ Q, const float* __restrict__ K,
            const float* __restrict__ V, float* __restrict__ O)
{
    extern __shared__ float sh[];
    float* Sc   = sh;                       // [128][388]
    float* KV   = sh + 128 * SC_LD;         // [128][64]
    float* rinv = KV + 128 * 64;            // [128]

    const int tid  = threadIdx.x;
    const int warp = tid >> 5;
    const int n    = blockIdx.x & 63;
    const int h    = (blockIdx.x >> 6) & 15;
    const int b    = blockIdx.x >> 10;
    const size_t base = ((size_t)(b * NHEADS + h)) * SEQ * HD;

    // Q fragments (register-resident across all key blocks)
    wmma::fragment<wmma::matrix_a, 16, 16, 8, wmma::precision::tf32, wmma::row_major> qf[8];
    {
        const float* qptr = Q + base + (size_t)(n * BS + warp * 16) * HD;
#pragma unroll
        for (int ks = 0; ks < 8; ks++) {
            wmma::load_matrix_sync(qf[ks], qptr + ks * 8, HD);
            frag_to_tf32(qf[ks]);
        }
    }

    // ---- scores: S[:, j*128 : j*128+128] = Q @ Kj^T ----
    for (int j = 0; j < 3; j++) {
        const int kblk = (n - 1 + j) * BS;
#pragma unroll
        for (int i = 0; i < 8; i++) {
            int idx = tid + i * 256;      // 2048 float4 = 128x16
            int r   = idx >> 4;
            int c4  = (idx & 15) << 2;
            int kpos = kblk + r;
            float4 val;
            if (kpos >= 0 && kpos < SEQ)
                val = *(const float4*)&K[base + (size_t)kpos * HD + c4];
            else
                val = make_float4(0.f, 0.f, 0.f, 0.f);
            *(float4*)&KV[r * HD + c4] = val;
        }
        __syncthreads();

        for (int nt = 0; nt < 8; nt++) {
            wmma::fragment<wmma::accumulator, 16, 16, 8, float> sacc;
            wmma::fill_fragment(sacc, 0.0f);
#pragma unroll
            for (int ks = 0; ks < 8; ks++) {
                wmma::fragment<wmma::matrix_b, 16, 16, 8, wmma::precision::tf32, wmma::col_major> bf;
                wmma::load_matrix_sync(bf, &KV[(nt * 16) * HD + ks * 8], HD);
                frag_to_tf32(bf);
                wmma::mma_sync(sacc, qf[ks], bf, sacc);
            }
            wmma::store_matrix_sync(&Sc[(warp * 16) * SC_LD + j * BS + nt * 16],
                                    sacc, SC_LD, wmma::mem_row_major);
        }
        __syncthreads();
    }

    // ---- masked softmax (one thread per query row) ----
    if (tid < 128) {
        const int q = tid;
        float* row = &Sc[q * SC_LD];
        const int kbase = (n - 1) * BS;
        const int lo = q;              // |kk - 128 - q| <= 128  ->  kk in [q, q+256]
        const int hi = q + 256;

        float m = -1e30f;
        for (int kk = lo; kk <= hi; kk++) {
            int kpos = kbase + kk;
            if (kpos < 0 || kpos >= SEQ) continue;
            float v = row[kk] * 0.125f;
            m = fmaxf(m, v);
        }
        float ssum = 0.f;
        for (int kk = 0; kk < 3 * BS; kk++) {
            int kpos = kbase + kk;
            float p = 0.f;
            if (kk >= lo && kk <= hi && kpos >= 0 && kpos < SEQ)
                p = __expf(row[kk] * 0.125f - m);
            row[kk] = p;
            ssum += p;
        }
        rinv[q] = 1.0f / ssum;
    }
    __syncthreads();

    // ---- O = P @ Vctx ----
    wmma::fragment<wmma::accumulator, 16, 16, 8, float> of[4];
#pragma unroll
    for (int dt = 0; dt < 4; dt++) wmma::fill_fragment(of[dt], 0.0f);

    for (int j = 0; j < 3; j++) {
        const int kblk = (n - 1 + j) * BS;
#pragma unroll
        for (int i = 0; i < 8; i++) {
            int idx = tid + i * 256;
            int r   = idx >> 4;
            int c4  = (idx & 15) << 2;
            int kpos = kblk + r;
            float4 val;
            if (kpos >= 0 && kpos < SEQ)
                val = *(const float4*)&V[base + (size_t)kpos * HD + c4];
            else
                val = make_float4(0.f, 0.f, 0.f, 0.f);
            *(float4*)&KV[r * HD + c4] = val;
        }
        __syncthreads();

        for (int ks = 0; ks < 16; ks++) {
            wmma::fragment<wmma::matrix_a, 16, 16, 8, wmma::precision::tf32, wmma::row_major> pf;
            wmma::load_matrix_sync(pf, &Sc[(warp * 16) * SC_LD + j * BS + ks * 8], SC_LD);
            frag_to_tf32(pf);
#pragma unroll
            for (int dt = 0; dt < 4; dt++) {
                wmma::fragment<wmma::matrix_b, 16, 16, 8, wmma::precision::tf32, wmma::row_major> vf;
                wmma::load_matrix_sync(vf, &KV[(ks * 8) * HD + dt * 16], HD);
                frag_to_tf32(vf);
                wmma::mma_sync(of[dt], pf, vf, of[dt]);
            }
        }
        __syncthreads();
    }

    // ---- stage O, scale by 1/rowsum, write out as [B,S,D] ----
    float* stg = Sc;   // reuse [128][68]
#pragma unroll
    for (int dt = 0; dt < 4; dt++)
        wmma::store_matrix_sync(&stg[(warp * 16) * 68 + dt * 16], of[dt], 68,
                                wmma::mem_row_major);
    __syncthreads();

#pragma unroll
    for (int i = 0; i < 8; i++) {
        int idx = tid + i * 256;       // 2048 float4 = 128 x 16
        int r   = idx >> 4;
        int c4  = (idx & 15) << 2;
        float s = rinv[r];
        float4 v = *(float4*)&stg[r * 68 + c4];
        v.x *= s; v.y *= s; v.z *= s; v.w *= s;
        *(float4*)&O[((size_t)b * SEQ + (size_t)n * BS + r) * DMODEL + h * HD + c4] = v;
    }
}

// ---------------------------------------------------------------------------
// Launch
// ---------------------------------------------------------------------------
extern "C" void kernel_launch(void* const* d_in, const int* in_sizes, int n_in,
                              void* d_out, int out_size)
{
    const float* x  = (const float*)d_in[0];
    const float* Wq = (const float*)d_in[1];
    const float* bq = (const float*)d_in[2];
    const float* Wk = (const float*)d_in[3];
    const float* bk = (const float*)d_in[4];
    const float* Wv = (const float*)d_in[5];
    const float* bv = (const float*)d_in[6];
    const float* Wo = (const float*)d_in[7];
    const float* bo = (const float*)d_in[8];
    float* out = (float*)d_out;

    float *qp, *kp, *vp, *ap;
    cudaGetSymbolAddress((void**)&qp, g_q);
    cudaGetSymbolAddress((void**)&kp, g_k);
    cudaGetSymbolAddress((void**)&vp, g_v);
    cudaGetSymbolAddress((void**)&ap, g_attn);

    const int gemm_smem = 128 * 132 * 4;                      // 67584 (staging is max)
    const int attn_smem = (128 * SC_LD + 128 * 64 + 128) * 4; // 231936

    cudaFuncSetAttribute(gemm_tf32_kernel<0>,
                         cudaFuncAttributeMaxDynamicSharedMemorySize, gemm_smem);
    cudaFuncSetAttribute(gemm_tf32_kernel<1>,
                         cudaFuncAttributeMaxDynamicSharedMemorySize, gemm_smem);
    cudaFuncSetAttribute(attn_kernel,
                         cudaFuncAttributeMaxDynamicSharedMemorySize, attn_smem);

    dim3 ggrid(DMODEL / 128, (BATCH * SEQ) / 128);  // (8, 128)

    gemm_tf32_kernel<1><<<ggrid, 256, gemm_smem>>>(x, Wq, bq, qp);
    gemm_tf32_kernel<1><<<ggrid, 256, gemm_smem>>>(x, Wk, bk, kp);
    gemm_tf32_kernel<1><<<ggrid, 256, gemm_smem>>>(x, Wv, bv, vp);

    attn_kernel<<<BATCH * NHEADS * NBLK, 256, attn_smem>>>(qp, kp, vp, ap);

    gemm_tf32_kernel<0><<<ggrid, 256, gemm_smem>>>(ap, Wo, bo, out);
}

// round 5
// speedup vs baseline: 2.0331x; 2.0331x over previous
#include <cuda_runtime.h>
#include <cuda_fp16.h>
#include <mma.h>
#include <cstdint>

using namespace nvcuda;

#define BATCH   2
#define SEQ     8192
#define DMODEL  1024
#define NHEADS  16
#define HD      64
#define NBLK    64
#define BS      128

// ---------------------------------------------------------------------------
// Device scratch
// ---------------------------------------------------------------------------
__device__ __half g_xh[(size_t)BATCH * SEQ * DMODEL];        // 32 MB (fp16 GEMM input)
__device__ __half g_wq[(size_t)DMODEL * DMODEL];
__device__ __half g_wk[(size_t)DMODEL * DMODEL];
__device__ __half g_wv[(size_t)DMODEL * DMODEL];
__device__ __half g_wo[(size_t)DMODEL * DMODEL];
__device__ float  g_q[(size_t)BATCH * NHEADS * SEQ * HD];    // fp32 (round-1 attn I/O)
__device__ float  g_k[(size_t)BATCH * NHEADS * SEQ * HD];
__device__ float  g_v[(size_t)BATCH * NHEADS * SEQ * HD];
__device__ float  g_attn[(size_t)BATCH * SEQ * DMODEL];
__device__ __half g_attnh[(size_t)BATCH * SEQ * DMODEL];     // fp16 copy for final GEMM

// ---------------------------------------------------------------------------
// fp32 -> fp16 conversion
// ---------------------------------------------------------------------------
__global__ void f2h_kernel(const float* __restrict__ src, __half* __restrict__ dst, int n4)
{
    int i = blockIdx.x * blockDim.x + threadIdx.x;
    for (; i < n4; i += gridDim.x * blockDim.x) {
        float4 v = *(const float4*)(src + (size_t)i * 4);
        __half2 lo = __floats2half2_rn(v.x, v.y);
        __half2 hi = __floats2half2_rn(v.z, v.w);
        uint2 o;
        o.x = *(uint32_t*)&lo;
        o.y = *(uint32_t*)&hi;
        *(uint2*)(dst + (size_t)i * 4) = o;
    }
}

// ---------------------------------------------------------------------------
// cp.async helpers
// ---------------------------------------------------------------------------
__device__ __forceinline__ uint32_t smem_u32(const void* p) {
    uint32_t a;
    asm("{ .reg .u64 t; cvta.to.shared.u64 t, %1; cvt.u32.u64 %0, t; }" : "=r"(a) : "l"(p));
    return a;
}
#define CP_ASYNC16(dst, src) \
    asm volatile("cp.async.cg.shared.global [%0], [%1], 16;" :: "r"(dst), "l"(src))
#define CP_COMMIT() asm volatile("cp.async.commit_group;")
#define CP_WAIT(N)  asm volatile("cp.async.wait_group %0;" :: "n"(N) : "memory")

// ---------------------------------------------------------------------------
// fp16 GEMM: C[M,N](fp32) = A[M,K]h @ W[N,K]h^T + bias
// M=16384, N=K=1024. BM=BN=128, BK=64, 3-stage cp.async pipeline.
// LAYOUT 0: C fp32 row-major [M,N]   LAYOUT 1: C fp32 [B,H,S,hd]
// ---------------------------------------------------------------------------
#define BKH   64
#define LDH   72              // half stride (64 + 8 pad)
#define NST   3
#define NCH   (DMODEL / BKH)  // 16
#define TILE_HBYTES (128 * LDH * 2)                 // 18432
#define STAGE_BYTES (2 * TILE_HBYTES)               // 36864
#define GEMM_SMEM   (NST * STAGE_BYTES)             // 110592

template <int LAYOUT>
__global__ void __launch_bounds__(256, 2)
gemm_h_kernel(const __half* __restrict__ A, const __half* __restrict__ W,
              const float* __restrict__ bias, float* __restrict__ C)
{
    extern __shared__ __align__(128) char smem[];
    const uint32_t sbase = smem_u32(smem);
    const int tid  = threadIdx.x;
    const int warp = tid >> 5;
    const int wm   = warp & 3;
    const int wn   = warp >> 2;
    const int m0   = blockIdx.y * 128;
    const int n0   = blockIdx.x * 128;

    const __half* Abase = A + (size_t)m0 * DMODEL;
    const __half* Bbase = W + (size_t)n0 * DMODEL;

    wmma::fragment<wmma::accumulator, 16, 16, 16, float> acc[2][4];
#pragma unroll
    for (int i = 0; i < 2; i++)
#pragma unroll
        for (int j = 0; j < 4; j++)
            wmma::fill_fragment(acc[i][j], 0.0f);

    auto load_stage = [&](int c, int s) {
        const int k0 = c * BKH;
        uint32_t sa = sbase + s * STAGE_BYTES;
#pragma unroll
        for (int i = 0; i < 4; i++) {
            int idx = tid + i * 256;
            int r = idx >> 3, ch = (idx & 7) << 3;
            CP_ASYNC16(sa + (r * LDH + ch) * 2,
                       Abase + (size_t)r * DMODEL + k0 + ch);
        }
#pragma unroll
        for (int i = 0; i < 4; i++) {
            int idx = tid + i * 256;
            int r = idx >> 3, ch = (idx & 7) << 3;
            CP_ASYNC16(sa + TILE_HBYTES + (r * LDH + ch) * 2,
                       Bbase + (size_t)r * DMODEL + k0 + ch);
        }
    };

    load_stage(0, 0); CP_COMMIT();
    load_stage(1, 1); CP_COMMIT();

    for (int c = 0; c < NCH; c++) {
        const int s = c % NST;
        CP_WAIT(1);
        __syncthreads();

        if (c + NST - 1 < NCH) load_stage(c + NST - 1, (c + NST - 1) % NST);
        CP_COMMIT();

        const __half* As = (const __half*)(smem + s * STAGE_BYTES);
        const __half* Bs = (const __half*)(smem + s * STAGE_BYTES + TILE_HBYTES);
#pragma unroll
        for (int ks = 0; ks < BKH / 16; ks++) {
            wmma::fragment<wmma::matrix_a, 16, 16, 16, __half, wmma::row_major> af[2];
#pragma unroll
            for (int i = 0; i < 2; i++)
                wmma::load_matrix_sync(af[i], As + (wm * 32 + i * 16) * LDH + ks * 16, LDH);
#pragma unroll
            for (int j = 0; j < 4; j++) {
                wmma::fragment<wmma::matrix_b, 16, 16, 16, __half, wmma::col_major> bf;
                wmma::load_matrix_sync(bf, Bs + (wn * 64 + j * 16) * LDH + ks * 16, LDH);
#pragma unroll
                for (int i = 0; i < 2; i++)
                    wmma::mma_sync(acc[i][j], af[i], bf, acc[i][j]);
            }
        }
        __syncthreads();
    }

    // Drain all async copies before reusing smem for the epilogue
    CP_WAIT(0);
    __syncthreads();

    float* stg = (float*)smem;   // 128 x 132 fp32 = 67584 <= 110592
#pragma unroll
    for (int i = 0; i < 2; i++)
#pragma unroll
        for (int j = 0; j < 4; j++)
            wmma::store_matrix_sync(&stg[(wm * 32 + i * 16) * 132 + wn * 64 + j * 16],
                                    acc[i][j], 132, wmma::mem_row_major);
    __syncthreads();

#pragma unroll
    for (int i = 0; i < 16; i++) {
        int idx = tid + i * 256;        // 4096 quads
        int r   = idx >> 5;
        int c4  = (idx & 31) << 2;
        float4 v = *(float4*)&stg[r * 132 + c4];
        float4 bv = *(const float4*)&bias[n0 + c4];
        v.x += bv.x; v.y += bv.y; v.z += bv.z; v.w += bv.w;

        if (LAYOUT == 0) {
            *(float4*)&C[(size_t)(m0 + r) * DMODEL + n0 + c4] = v;
        } else {
            int m  = m0 + r;
            int bb = m >> 13;
            int ss = m & (SEQ - 1);
            int nn = n0 + c4;
            int h  = nn >> 6;
            int d0 = nn & 63;
            *(float4*)&C[(((size_t)bb * NHEADS + h) * SEQ + ss) * HD + d0] = v;
        }
    }
}

// ---------------------------------------------------------------------------
// Attention kernel — ROUND-1 VERBATIM (tf32 WMMA, fp32 I/O, known-passing)
// ---------------------------------------------------------------------------
template <typename Frag>
__device__ __forceinline__ void frag_to_tf32(Frag& f) {
#pragma unroll
    for (int i = 0; i < f.num_elements; i++)
        f.x[i] = wmma::__float_to_tf32(f.x[i]);
}

#define SC_LD 388
#define ATTN_SMEM ((128 * SC_LD + 128 * 64 + 128) * 4)

__global__ void __launch_bounds__(256, 1)
attn_kernel(const float* __restrict__ Q, const float* __restrict__ K,
            const float* __restrict__ V, float* __restrict__ O)
{
    extern __shared__ float sh[];
    float* Sc   = sh;
    float* KV   = sh + 128 * SC_LD;
    float* rinv = KV + 128 * 64;

    const int tid  = threadIdx.x;
    const int warp = tid >> 5;
    const int n    = blockIdx.x & 63;
    const int h    = (blockIdx.x >> 6) & 15;
    const int b    = blockIdx.x >> 10;
    const size_t base = ((size_t)(b * NHEADS + h)) * SEQ * HD;

    wmma::fragment<wmma::matrix_a, 16, 16, 8, wmma::precision::tf32, wmma::row_major> qf[8];
    {
        const float* qptr = Q + base + (size_t)(n * BS + warp * 16) * HD;
#pragma unroll
        for (int ks = 0; ks < 8; ks++) {
            wmma::load_matrix_sync(qf[ks], qptr + ks * 8, HD);
            frag_to_tf32(qf[ks]);
        }
    }

    for (int j = 0; j < 3; j++) {
        const int kblk = (n - 1 + j) * BS;
#pragma unroll
        for (int i = 0; i < 8; i++) {
            int idx = tid + i * 256;
            int r   = idx >> 4;
            int c4  = (idx & 15) << 2;
            int kpos = kblk + r;
            float4 val;
            if (kpos >= 0 && kpos < SEQ)
                val = *(const float4*)&K[base + (size_t)kpos * HD + c4];
            else
                val = make_float4(0.f, 0.f, 0.f, 0.f);
            *(float4*)&KV[r * HD + c4] = val;
        }
        __syncthreads();

        for (int nt = 0; nt < 8; nt++) {
            wmma::fragment<wmma::accumulator, 16, 16, 8, float> sacc;
            wmma::fill_fragment(sacc, 0.0f);
#pragma unroll
            for (int ks = 0; ks < 8; ks++) {
                wmma::fragment<wmma::matrix_b, 16, 16, 8, wmma::precision::tf32, wmma::col_major> bf;
                wmma::load_matrix_sync(bf, &KV[(nt * 16) * HD + ks * 8], HD);
                frag_to_tf32(bf);
                wmma::mma_sync(sacc, qf[ks], bf, sacc);
            }
            wmma::store_matrix_sync(&Sc[(warp * 16) * SC_LD + j * BS + nt * 16],
                                    sacc, SC_LD, wmma::mem_row_major);
        }
        __syncthreads();
    }

    if (tid < 128) {
        const int q = tid;
        float* row = &Sc[q * SC_LD];
        const int kbase = (n - 1) * BS;
        const int lo = q;
        const int hi = q + 256;

        float m = -1e30f;
        for (int kk = lo; kk <= hi; kk++) {
            int kpos = kbase + kk;
            if (kpos < 0 || kpos >= SEQ) continue;
            float v = row[kk] * 0.125f;
            m = fmaxf(m, v);
        }
        float ssum = 0.f;
        for (int kk = 0; kk < 3 * BS; kk++) {
            int kpos = kbase + kk;
            float p = 0.f;
            if (kk >= lo && kk <= hi && kpos >= 0 && kpos < SEQ)
                p = __expf(row[kk] * 0.125f - m);
            row[kk] = p;
            ssum += p;
        }
        rinv[q] = 1.0f / ssum;
    }
    __syncthreads();

    wmma::fragment<wmma::accumulator, 16, 16, 8, float> of[4];
#pragma unroll
    for (int dt = 0; dt < 4; dt++) wmma::fill_fragment(of[dt], 0.0f);

    for (int j = 0; j < 3; j++) {
        const int kblk = (n - 1 + j) * BS;
#pragma unroll
        for (int i = 0; i < 8; i++) {
            int idx = tid + i * 256;
            int r   = idx >> 4;
            int c4  = (idx & 15) << 2;
            int kpos = kblk + r;
            float4 val;
            if (kpos >= 0 && kpos < SEQ)
                val = *(const float4*)&V[base + (size_t)kpos * HD + c4];
            else
                val = make_float4(0.f, 0.f, 0.f, 0.f);
            *(float4*)&KV[r * HD + c4] = val;
        }
        __syncthreads();

        for (int ks = 0; ks < 16; ks++) {
            wmma::fragment<wmma::matrix_a, 16, 16, 8, wmma::precision::tf32, wmma::row_major> pf;
            wmma::load_matrix_sync(pf, &Sc[(warp * 16) * SC_LD + j * BS + ks * 8], SC_LD);
            frag_to_tf32(pf);
#pragma unroll
            for (int dt = 0; dt < 4; dt++) {
                wmma::fragment<wmma::matrix_b, 16, 16, 8, wmma::precision::tf32, wmma::row_major> vf;
                wmma::load_matrix_sync(vf, &KV[(ks * 8) * HD + dt * 16], HD);
                frag_to_tf32(vf);
                wmma::mma_sync(of[dt], pf, vf, of[dt]);
            }
        }
        __syncthreads();
    }

    float* stg = Sc;
#pragma unroll
    for (int dt = 0; dt < 4; dt++)
        wmma::store_matrix_sync(&stg[(warp * 16) * 68 + dt * 16], of[dt], 68,
                                wmma::mem_row_major);
    __syncthreads();

#pragma unroll
    for (int i = 0; i < 8; i++) {
        int idx = tid + i * 256;
        int r   = idx >> 4;
        int c4  = (idx & 15) << 2;
        float s = rinv[r];
        float4 v = *(float4*)&stg[r * 68 + c4];
        v.x *= s; v.y *= s; v.z *= s; v.w *= s;
        *(float4*)&O[((size_t)b * SEQ + (size_t)n * BS + r) * DMODEL + h * HD + c4] = v;
    }
}

// ---------------------------------------------------------------------------
// Launch
// ---------------------------------------------------------------------------
extern "C" void kernel_launch(void* const* d_in, const int* in_sizes, int n_in,
                              void* d_out, int out_size)
{
    const float* x  = (const float*)d_in[0];
    const float* Wq = (const float*)d_in[1];
    const float* bq = (const float*)d_in[2];
    const float* Wk = (const float*)d_in[3];
    const float* bk = (const float*)d_in[4];
    const float* Wv = (const float*)d_in[5];
    const float* bv = (const float*)d_in[6];
    const float* Wo = (const float*)d_in[7];
    const float* bo = (const float*)d_in[8];
    float* out = (float*)d_out;

    __half *xh, *wq, *wk, *wv, *wo, *ah;
    float  *qp, *kp, *vp, *ap;
    cudaGetSymbolAddress((void**)&xh, g_xh);
    cudaGetSymbolAddress((void**)&wq, g_wq);
    cudaGetSymbolAddress((void**)&wk, g_wk);
    cudaGetSymbolAddress((void**)&wv, g_wv);
    cudaGetSymbolAddress((void**)&wo, g_wo);
    cudaGetSymbolAddress((void**)&ah, g_attnh);
    cudaGetSymbolAddress((void**)&qp, g_q);
    cudaGetSymbolAddress((void**)&kp, g_k);
    cudaGetSymbolAddress((void**)&vp, g_v);
    cudaGetSymbolAddress((void**)&ap, g_attn);

    cudaFuncSetAttribute(gemm_h_kernel<0>,
                         cudaFuncAttributeMaxDynamicSharedMemorySize, GEMM_SMEM);
    cudaFuncSetAttribute(gemm_h_kernel<1>,
                         cudaFuncAttributeMaxDynamicSharedMemorySize, GEMM_SMEM);
    cudaFuncSetAttribute(attn_kernel,
                         cudaFuncAttributeMaxDynamicSharedMemorySize, ATTN_SMEM);

    const int XN4 = (BATCH * SEQ * DMODEL) / 4;
    const int WN4 = (DMODEL * DMODEL) / 4;
    f2h_kernel<<<592, 256>>>(x,  xh, XN4);
    f2h_kernel<<<296, 256>>>(Wq, wq, WN4);
    f2h_kernel<<<296, 256>>>(Wk, wk, WN4);
    f2h_kernel<<<296, 256>>>(Wv, wv, WN4);
    f2h_kernel<<<296, 256>>>(Wo, wo, WN4);

    dim3 ggrid(DMODEL / 128, (BATCH * SEQ) / 128);   // (8,128)
    gemm_h_kernel<1><<<ggrid, 256, GEMM_SMEM>>>(xh, wq, bq, qp);
    gemm_h_kernel<1><<<ggrid, 256, GEMM_SMEM>>>(xh, wk, bk, kp);
    gemm_h_kernel<1><<<ggrid, 256, GEMM_SMEM>>>(xh, wv, bv, vp);

    attn_kernel<<<BATCH * NHEADS * NBLK, 256, ATTN_SMEM>>>(qp, kp, vp, ap);

    // fp32 attn output -> fp16 for the final fp16 GEMM
    f2h_kernel<<<592, 256>>>(ap, ah, XN4);

    gemm_h_kernel<0><<<ggrid, 256, GEMM_SMEM>>>(ah, wo, bo, out);
}

// round 6
// speedup vs baseline: 4.2441x; 2.0875x over previous
#include <cuda_runtime.h>
#include <cuda_fp16.h>
#include <mma.h>
#include <cstdint>

using namespace nvcuda;

#define BATCH   2
#define SEQ     8192
#define DMODEL  1024
#define NHEADS  16
#define HD      64
#define NBLK    64
#define BS      128

// ---------------------------------------------------------------------------
// Device scratch
// ---------------------------------------------------------------------------
__device__ __half g_xh[(size_t)BATCH * SEQ * DMODEL];        // fp16 GEMM input
__device__ __half g_wq[(size_t)DMODEL * DMODEL];
__device__ __half g_wk[(size_t)DMODEL * DMODEL];
__device__ __half g_wv[(size_t)DMODEL * DMODEL];
__device__ __half g_wo[(size_t)DMODEL * DMODEL];
__device__ float  g_q[(size_t)BATCH * NHEADS * SEQ * HD];    // fp32 q/k/v
__device__ float  g_k[(size_t)BATCH * NHEADS * SEQ * HD];
__device__ float  g_v[(size_t)BATCH * NHEADS * SEQ * HD];
__device__ __half g_attnh[(size_t)BATCH * SEQ * DMODEL];     // fp16 attn out

// ---------------------------------------------------------------------------
// fp32 -> fp16 conversion
// ---------------------------------------------------------------------------
__global__ void f2h_kernel(const float* __restrict__ src, __half* __restrict__ dst, int n4)
{
    int i = blockIdx.x * blockDim.x + threadIdx.x;
    for (; i < n4; i += gridDim.x * blockDim.x) {
        float4 v = *(const float4*)(src + (size_t)i * 4);
        __half2 lo = __floats2half2_rn(v.x, v.y);
        __half2 hi = __floats2half2_rn(v.z, v.w);
        uint2 o;
        o.x = *(uint32_t*)&lo;
        o.y = *(uint32_t*)&hi;
        *(uint2*)(dst + (size_t)i * 4) = o;
    }
}

// ---------------------------------------------------------------------------
// cp.async helpers
// ---------------------------------------------------------------------------
__device__ __forceinline__ uint32_t smem_u32(const void* p) {
    uint32_t a;
    asm("{ .reg .u64 t; cvta.to.shared.u64 t, %1; cvt.u32.u64 %0, t; }" : "=r"(a) : "l"(p));
    return a;
}
#define CP_ASYNC16(dst, src) \
    asm volatile("cp.async.cg.shared.global [%0], [%1], 16;" :: "r"(dst), "l"(src))
#define CP_COMMIT() asm volatile("cp.async.commit_group;")
#define CP_WAIT(N)  asm volatile("cp.async.wait_group %0;" :: "n"(N) : "memory")

// ---------------------------------------------------------------------------
// fp16 GEMM (UNCHANGED, banked): C[M,N](fp32) = A@W^T + bias
// ---------------------------------------------------------------------------
#define BKH   64
#define LDH   72
#define NST   3
#define NCH   (DMODEL / BKH)
#define TILE_HBYTES (128 * LDH * 2)
#define STAGE_BYTES (2 * TILE_HBYTES)
#define GEMM_SMEM   (NST * STAGE_BYTES)

template <int LAYOUT>
__global__ void __launch_bounds__(256, 2)
gemm_h_kernel(const __half* __restrict__ A, const __half* __restrict__ W,
              const float* __restrict__ bias, float* __restrict__ C)
{
    extern __shared__ __align__(128) char smem[];
    const uint32_t sbase = smem_u32(smem);
    const int tid  = threadIdx.x;
    const int warp = tid >> 5;
    const int wm   = warp & 3;
    const int wn   = warp >> 2;
    const int m0   = blockIdx.y * 128;
    const int n0   = blockIdx.x * 128;

    const __half* Abase = A + (size_t)m0 * DMODEL;
    const __half* Bbase = W + (size_t)n0 * DMODEL;

    wmma::fragment<wmma::accumulator, 16, 16, 16, float> acc[2][4];
#pragma unroll
    for (int i = 0; i < 2; i++)
#pragma unroll
        for (int j = 0; j < 4; j++)
            wmma::fill_fragment(acc[i][j], 0.0f);

    auto load_stage = [&](int c, int s) {
        const int k0 = c * BKH;
        uint32_t sa = sbase + s * STAGE_BYTES;
#pragma unroll
        for (int i = 0; i < 4; i++) {
            int idx = tid + i * 256;
            int r = idx >> 3, ch = (idx & 7) << 3;
            CP_ASYNC16(sa + (r * LDH + ch) * 2,
                       Abase + (size_t)r * DMODEL + k0 + ch);
        }
#pragma unroll
        for (int i = 0; i < 4; i++) {
            int idx = tid + i * 256;
            int r = idx >> 3, ch = (idx & 7) << 3;
            CP_ASYNC16(sa + TILE_HBYTES + (r * LDH + ch) * 2,
                       Bbase + (size_t)r * DMODEL + k0 + ch);
        }
    };

    load_stage(0, 0); CP_COMMIT();
    load_stage(1, 1); CP_COMMIT();

    for (int c = 0; c < NCH; c++) {
        const int s = c % NST;
        CP_WAIT(1);
        __syncthreads();

        if (c + NST - 1 < NCH) load_stage(c + NST - 1, (c + NST - 1) % NST);
        CP_COMMIT();

        const __half* As = (const __half*)(smem + s * STAGE_BYTES);
        const __half* Bs = (const __half*)(smem + s * STAGE_BYTES + TILE_HBYTES);
#pragma unroll
        for (int ks = 0; ks < BKH / 16; ks++) {
            wmma::fragment<wmma::matrix_a, 16, 16, 16, __half, wmma::row_major> af[2];
#pragma unroll
            for (int i = 0; i < 2; i++)
                wmma::load_matrix_sync(af[i], As + (wm * 32 + i * 16) * LDH + ks * 16, LDH);
#pragma unroll
            for (int j = 0; j < 4; j++) {
                wmma::fragment<wmma::matrix_b, 16, 16, 16, __half, wmma::col_major> bf;
                wmma::load_matrix_sync(bf, Bs + (wn * 64 + j * 16) * LDH + ks * 16, LDH);
#pragma unroll
                for (int i = 0; i < 2; i++)
                    wmma::mma_sync(acc[i][j], af[i], bf, acc[i][j]);
            }
        }
        __syncthreads();
    }

    CP_WAIT(0);
    __syncthreads();

    float* stg = (float*)smem;
#pragma unroll
    for (int i = 0; i < 2; i++)
#pragma unroll
        for (int j = 0; j < 4; j++)
            wmma::store_matrix_sync(&stg[(wm * 32 + i * 16) * 132 + wn * 64 + j * 16],
                                    acc[i][j], 132, wmma::mem_row_major);
    __syncthreads();

#pragma unroll
    for (int i = 0; i < 16; i++) {
        int idx = tid + i * 256;
        int r   = idx >> 5;
        int c4  = (idx & 31) << 2;
        float4 v = *(float4*)&stg[r * 132 + c4];
        float4 bv = *(const float4*)&bias[n0 + c4];
        v.x += bv.x; v.y += bv.y; v.z += bv.z; v.w += bv.w;

        if (LAYOUT == 0) {
            *(float4*)&C[(size_t)(m0 + r) * DMODEL + n0 + c4] = v;
        } else {
            int m  = m0 + r;
            int bb = m >> 13;
            int ss = m & (SEQ - 1);
            int nn = n0 + c4;
            int h  = nn >> 6;
            int d0 = nn & 63;
            *(float4*)&C[(((size_t)bb * NHEADS + h) * SEQ + ss) * HD + d0] = v;
        }
    }
}

// ---------------------------------------------------------------------------
// Streaming fp16 attention. One CTA per (b,h,n): 128 queries, 6 key-blocks
// of 64. No-max softmax (scores bounded): single pass, running row sums.
// SMEM (63KB): Sc fp32 [128][68] | Ph half [128][72] | KVh half [64][72] | rsum
// ---------------------------------------------------------------------------
#define WKB 64                 // key block
#define NJ  6                  // (3*BS)/WKB
#define SCLD 68
#define PLD  72
#define OFF_PH  (128 * SCLD * 4)                 // 34816
#define OFF_KV  (OFF_PH + 128 * PLD * 2)         // 53248
#define OFF_RS  (OFF_KV + WKB * PLD * 2)         // 62464
#define ATTN_SMEM (OFF_RS + 512)                 // 62976

__global__ void __launch_bounds__(256)
attn_kernel(const float* __restrict__ Q, const float* __restrict__ K,
            const float* __restrict__ V, __half* __restrict__ O)
{
    extern __shared__ __align__(128) char smem[];
    float*  Sc   = (float*)smem;                  // [128][68]
    __half* Ph   = (__half*)(smem + OFF_PH);      // [128][72]
    __half* KVh  = (__half*)(smem + OFF_KV);      // [64][72]
    float*  rsum = (float*)(smem + OFF_RS);       // [128]

    const int tid  = threadIdx.x;
    const int warp = tid >> 5;
    const int n    = blockIdx.x & 63;
    const int h    = (blockIdx.x >> 6) & 15;
    const int b    = blockIdx.x >> 10;
    const size_t base = ((size_t)(b * NHEADS + h)) * SEQ * HD;
    const int kbase = (n - 1) * BS;

    // ---- Phase 0: Q fp32 -> half staging, then register fragments ----
    {
        const float* qb = Q + base + (size_t)(n * BS) * HD;
#pragma unroll
        for (int i = 0; i < 4; i++) {
            int idx = tid + i * 256;             // 1024 jobs: 128 rows x 8 col-chunks
            int r = idx >> 3, ch = (idx & 7) << 3;
            float4 f0 = *(const float4*)(qb + (size_t)r * HD + ch);
            float4 f1 = *(const float4*)(qb + (size_t)r * HD + ch + 4);
            __half2 a = __floats2half2_rn(f0.x, f0.y);
            __half2 bq2 = __floats2half2_rn(f0.z, f0.w);
            __half2 cc = __floats2half2_rn(f1.x, f1.y);
            __half2 d = __floats2half2_rn(f1.z, f1.w);
            uint4 o;
            o.x = *(uint32_t*)&a; o.y = *(uint32_t*)&bq2;
            o.z = *(uint32_t*)&cc; o.w = *(uint32_t*)&d;
            *(uint4*)(Ph + r * PLD + ch) = o;
        }
    }
    __syncthreads();

    wmma::fragment<wmma::matrix_a, 16, 16, 16, __half, wmma::row_major> qf[4];
#pragma unroll
    for (int ks = 0; ks < 4; ks++)
        wmma::load_matrix_sync(qf[ks], Ph + (warp * 16) * PLD + ks * 16, PLD);
    __syncthreads();   // Ph free for reuse

    // mask bounds for this thread's softmax row
    const int qrow = tid >> 1;
    const int par  = tid & 1;
    int klo = qrow;
    if (kbase < 0 && -kbase > klo) klo = -kbase;
    int khi = qrow + 256;
    {
        int lim = SEQ - kbase - 1;
        if (lim < khi) khi = lim;
    }
    float lsum = 0.f;

    wmma::fragment<wmma::accumulator, 16, 16, 16, float> of[4];
#pragma unroll
    for (int dt = 0; dt < 4; dt++) wmma::fill_fragment(of[dt], 0.0f);

    for (int j = 0; j < NJ; j++) {
        const int kblk = kbase + j * WKB;

        // ---- load K_j (64 x 64) fp32->half, zero-padded ----
#pragma unroll
        for (int i = 0; i < 2; i++) {
            int idx = tid + i * 256;             // 512 jobs: 64 rows x 8 chunks
            int r = idx >> 3, ch = (idx & 7) << 3;
            int kpos = kblk + r;
            uint4 o = make_uint4(0, 0, 0, 0);
            if (kpos >= 0 && kpos < SEQ) {
                const float* kp = K + base + (size_t)kpos * HD + ch;
                float4 f0 = *(const float4*)kp;
                float4 f1 = *(const float4*)(kp + 4);
                __half2 a = __floats2half2_rn(f0.x, f0.y);
                __half2 bb2 = __floats2half2_rn(f0.z, f0.w);
                __half2 cc = __floats2half2_rn(f1.x, f1.y);
                __half2 d = __floats2half2_rn(f1.z, f1.w);
                o.x = *(uint32_t*)&a; o.y = *(uint32_t*)&bb2;
                o.z = *(uint32_t*)&cc; o.w = *(uint32_t*)&d;
            }
            *(uint4*)(KVh + r * PLD + ch) = o;
        }
        __syncthreads();

        // ---- S_j = Q @ K_j^T  (128 x 64) ----
#pragma unroll
        for (int nt = 0; nt < 4; nt++) {
            wmma::fragment<wmma::accumulator, 16, 16, 16, float> sacc;
            wmma::fill_fragment(sacc, 0.0f);
#pragma unroll
            for (int ks = 0; ks < 4; ks++) {
                wmma::fragment<wmma::matrix_b, 16, 16, 16, __half, wmma::col_major> bf;
                wmma::load_matrix_sync(bf, KVh + (nt * 16) * PLD + ks * 16, PLD);
                wmma::mma_sync(sacc, qf[ks], bf, sacc);
            }
            wmma::store_matrix_sync(&Sc[(warp * 16) * SCLD + nt * 16], sacc,
                                    SCLD, wmma::mem_row_major);
        }
        __syncthreads();

        // ---- exp + mask -> P halves; accumulate row sums ----
        {
            float* row = &Sc[qrow * SCLD];
            __half* prow = Ph + qrow * PLD;
            const int c0 = par * 32;
#pragma unroll
            for (int c4 = 0; c4 < 32; c4 += 4) {
                int c = c0 + c4;
                float4 v = *(float4*)&row[c];
                float p0 = 0.f, p1 = 0.f, p2 = 0.f, p3 = 0.f;
                int kk = j * WKB + c;
                if (kk + 0 >= klo && kk + 0 <= khi) p0 = __expf(v.x * 0.125f);
                if (kk + 1 >= klo && kk + 1 <= khi) p1 = __expf(v.y * 0.125f);
                if (kk + 2 >= klo && kk + 2 <= khi) p2 = __expf(v.z * 0.125f);
                if (kk + 3 >= klo && kk + 3 <= khi) p3 = __expf(v.w * 0.125f);
                lsum += p0 + p1 + p2 + p3;
                __half2 lo = __floats2half2_rn(p0, p1);
                __half2 hi = __floats2half2_rn(p2, p3);
                uint2 o; o.x = *(uint32_t*)&lo; o.y = *(uint32_t*)&hi;
                *(uint2*)&prow[c] = o;
            }
        }

        // ---- load V_j (64 x 64) fp32->half, zero-padded ----
#pragma unroll
        for (int i = 0; i < 2; i++) {
            int idx = tid + i * 256;
            int r = idx >> 3, ch = (idx & 7) << 3;
            int kpos = kblk + r;
            uint4 o = make_uint4(0, 0, 0, 0);
            if (kpos >= 0 && kpos < SEQ) {
                const float* vp = V + base + (size_t)kpos * HD + ch;
                float4 f0 = *(const float4*)vp;
                float4 f1 = *(const float4*)(vp + 4);
                __half2 a = __floats2half2_rn(f0.x, f0.y);
                __half2 bb2 = __floats2half2_rn(f0.z, f0.w);
                __half2 cc = __floats2half2_rn(f1.x, f1.y);
                __half2 d = __floats2half2_rn(f1.z, f1.w);
                o.x = *(uint32_t*)&a; o.y = *(uint32_t*)&bb2;
                o.z = *(uint32_t*)&cc; o.w = *(uint32_t*)&d;
            }
            *(uint4*)(KVh + r * PLD + ch) = o;
        }
        __syncthreads();

        // ---- O += P_j @ V_j ----
#pragma unroll
        for (int ks = 0; ks < 4; ks++) {
            wmma::fragment<wmma::matrix_a, 16, 16, 16, __half, wmma::row_major> pf;
            wmma::load_matrix_sync(pf, Ph + (warp * 16) * PLD + ks * 16, PLD);
#pragma unroll
            for (int dt = 0; dt < 4; dt++) {
                wmma::fragment<wmma::matrix_b, 16, 16, 16, __half, wmma::row_major> vf;
                wmma::load_matrix_sync(vf, KVh + (ks * 16) * PLD + dt * 16, PLD);
                wmma::mma_sync(of[dt], pf, vf, of[dt]);
            }
        }
        __syncthreads();
    }

    // ---- row sums -> smem ----
    lsum += __shfl_xor_sync(0xFFFFFFFF, lsum, 1);
    if (par == 0) rsum[qrow] = 1.0f / lsum;

    // ---- stage O (Sc reuse), scale, write half [B,S,D] ----
#pragma unroll
    for (int dt = 0; dt < 4; dt++)
        wmma::store_matrix_sync(&Sc[(warp * 16) * SCLD + dt * 16], of[dt],
                                SCLD, wmma::mem_row_major);
    __syncthreads();

#pragma unroll
    for (int i = 0; i < 4; i++) {
        int idx = tid + i * 256;                 // 1024 jobs: 128 rows x 8 chunks
        int r = idx >> 3, ch = (idx & 7) << 3;
        float s = rsum[r];
        float4 f0 = *(float4*)&Sc[r * SCLD + ch];
        float4 f1 = *(float4*)&Sc[r * SCLD + ch + 4];
        __half2 a = __floats2half2_rn(f0.x * s, f0.y * s);
        __half2 bb2 = __floats2half2_rn(f0.z * s, f0.w * s);
        __half2 cc = __floats2half2_rn(f1.x * s, f1.y * s);
        __half2 d = __floats2half2_rn(f1.z * s, f1.w * s);
        uint4 o;
        o.x = *(uint32_t*)&a; o.y = *(uint32_t*)&bb2;
        o.z = *(uint32_t*)&cc; o.w = *(uint32_t*)&d;
        *(uint4*)&O[((size_t)b * SEQ + (size_t)n * BS + r) * DMODEL + h * HD + ch] = o;
    }
}

// ---------------------------------------------------------------------------
// Launch
// ---------------------------------------------------------------------------
extern "C" void kernel_launch(void* const* d_in, const int* in_sizes, int n_in,
                              void* d_out, int out_size)
{
    const float* x  = (const float*)d_in[0];
    const float* Wq = (const float*)d_in[1];
    const float* bq = (const float*)d_in[2];
    const float* Wk = (const float*)d_in[3];
    const float* bk = (const float*)d_in[4];
    const float* Wv = (const float*)d_in[5];
    const float* bv = (const float*)d_in[6];
    const float* Wo = (const float*)d_in[7];
    const float* bo = (const float*)d_in[8];
    float* out = (float*)d_out;

    __half *xh, *wq, *wk, *wv, *wo, *ah;
    float  *qp, *kp, *vp;
    cudaGetSymbolAddress((void**)&xh, g_xh);
    cudaGetSymbolAddress((void**)&wq, g_wq);
    cudaGetSymbolAddress((void**)&wk, g_wk);
    cudaGetSymbolAddress((void**)&wv, g_wv);
    cudaGetSymbolAddress((void**)&wo, g_wo);
    cudaGetSymbolAddress((void**)&ah, g_attnh);
    cudaGetSymbolAddress((void**)&qp, g_q);
    cudaGetSymbolAddress((void**)&kp, g_k);
    cudaGetSymbolAddress((void**)&vp, g_v);

    cudaFuncSetAttribute(gemm_h_kernel<0>,
                         cudaFuncAttributeMaxDynamicSharedMemorySize, GEMM_SMEM);
    cudaFuncSetAttribute(gemm_h_kernel<1>,
                         cudaFuncAttributeMaxDynamicSharedMemorySize, GEMM_SMEM);
    cudaFuncSetAttribute(attn_kernel,
                         cudaFuncAttributeMaxDynamicSharedMemorySize, ATTN_SMEM);

    const int XN4 = (BATCH * SEQ * DMODEL) / 4;
    const int WN4 = (DMODEL * DMODEL) / 4;
    f2h_kernel<<<592, 256>>>(x,  xh, XN4);
    f2h_kernel<<<296, 256>>>(Wq, wq, WN4);
    f2h_kernel<<<296, 256>>>(Wk, wk, WN4);
    f2h_kernel<<<296, 256>>>(Wv, wv, WN4);
    f2h_kernel<<<296, 256>>>(Wo, wo, WN4);

    dim3 ggrid(DMODEL / 128, (BATCH * SEQ) / 128);   // (8,128)
    gemm_h_kernel<1><<<ggrid, 256, GEMM_SMEM>>>(xh, wq, bq, qp);
    gemm_h_kernel<1><<<ggrid, 256, GEMM_SMEM>>>(xh, wk, bk, kp);
    gemm_h_kernel<1><<<ggrid, 256, GEMM_SMEM>>>(xh, wv, bv, vp);

    attn_kernel<<<BATCH * NHEADS * NBLK, 256, ATTN_SMEM>>>(qp, kp, vp, ah);

    gemm_h_kernel<0><<<ggrid, 256, GEMM_SMEM>>>(ah, wo, bo, out);
}